// round 1
// baseline (speedup 1.0000x reference)
#include <cuda_runtime.h>

#define IMG_W 1242
#define IMG_H 375
#define IMG_HW (IMG_H * IMG_W)
#define BMAX 32

// ---- scratch (device globals: allocation-free, zero-initialized at load) ----
__device__ double g_acc[3];                // [0] sum_{b,n} err, [1] sum_{b,w} derr, [2] transformation loss
__device__ float  g_predRT[BMAX * 12];     // per-batch [R|t] rows (3x4)
__device__ unsigned long long g_keys[(size_t)BMAX * IMG_HW];  // (n<<32)|float_bits(Z); 0 = empty

// ---------------------------------------------------------------------------
// K0: Rodrigues for predicted rotation, transformation loss, reset accumulators
// ---------------------------------------------------------------------------
__global__ void k0_prep(const float* __restrict__ gt_t, const float* __restrict__ gt_r,
                        const float* __restrict__ pr_t, const float* __restrict__ pr_r, int B) {
    int b = threadIdx.x;  // launched with 32 threads
    float st = 0.f, sr = 0.f;
    if (b < B) {
        float rx = pr_r[3*b+0], ry = pr_r[3*b+1], rz = pr_r[3*b+2];
        float th2 = rx*rx + ry*ry + rz*rz;
        float th  = sqrtf(th2);
        float A   = sinf(th) / th;
        float Bc  = (1.0f - cosf(th)) / th2;
        float* M = g_predRT + b * 12;
        // R = I + A*K + Bc*(r r^T - th2 I)
        M[0]  = 1.f + Bc*(rx*rx - th2); M[1]  = -A*rz + Bc*rx*ry;       M[2]  =  A*ry + Bc*rx*rz;       M[3]  = pr_t[3*b+0];
        M[4]  =  A*rz + Bc*rx*ry;       M[5]  = 1.f + Bc*(ry*ry - th2); M[6]  = -A*rx + Bc*ry*rz;       M[7]  = pr_t[3*b+1];
        M[8]  = -A*ry + Bc*rx*rz;       M[9]  =  A*rx + Bc*ry*rz;       M[10] = 1.f + Bc*(rz*rz - th2); M[11] = pr_t[3*b+2];
        #pragma unroll
        for (int i = 0; i < 3; i++) {
            float dt = pr_t[3*b+i] - gt_t[3*b+i]; st += dt*dt;
            float dr = pr_r[3*b+i] - gt_r[3*b+i]; sr += dr*dr;
        }
    }
    #pragma unroll
    for (int o = 16; o > 0; o >>= 1) {
        st += __shfl_down_sync(0xffffffffu, st, o);
        sr += __shfl_down_sync(0xffffffffu, sr, o);
    }
    if (b == 0) {
        g_acc[0] = 0.0;
        g_acc[1] = 0.0;
        g_acc[2] = 2.0 * ((double)st / B) + (double)sr / B;   // TRANS_W=2, ROT_W=1
    }
}

// ---------------------------------------------------------------------------
// K1: per-point transform (pred & gt), point-cloud err, project + scatter
// ---------------------------------------------------------------------------
__global__ void __launch_bounds__(256) k1_points(const float4* __restrict__ pts,
                                                 const float* __restrict__ gt_rt,   // B x 16
                                                 const float* __restrict__ kmat,    // 9
                                                 int B, int N) {
    int tid = blockIdx.x * blockDim.x + threadIdx.x;
    float err = 0.f;
    if (tid < B * N) {
        int b = tid / N;
        float4 p = pts[tid];
        const float* Mp = g_predRT + b * 12;
        const float* Mg = gt_rt + b * 16;
        float X  = fmaf(Mp[0], p.x, fmaf(Mp[1], p.y, fmaf(Mp[2],  p.z, Mp[3])));
        float Y  = fmaf(Mp[4], p.x, fmaf(Mp[5], p.y, fmaf(Mp[6],  p.z, Mp[7])));
        float Zc = fmaf(Mp[8], p.x, fmaf(Mp[9], p.y, fmaf(Mp[10], p.z, Mp[11])));
        float Xg = fmaf(Mg[0], p.x, fmaf(Mg[1], p.y, fmaf(Mg[2],  p.z, Mg[3])));
        float Yg = fmaf(Mg[4], p.x, fmaf(Mg[5], p.y, fmaf(Mg[6],  p.z, Mg[7])));
        float Zg = fmaf(Mg[8], p.x, fmaf(Mg[9], p.y, fmaf(Mg[10], p.z, Mg[11])));
        float dx = X - Xg, dy = Y - Yg, dz = Zc - Zg;
        err = sqrtf(dx*dx + dy*dy + dz*dz);
        if (Zc > 0.f) {
            float fx = kmat[0], cx = kmat[2], fy = kmat[4], cy = kmat[5];
            float px = (fx * X + cx * Zc) / Zc;
            float py = (fy * Y + cy * Zc) / Zc;
            px = fminf(fmaxf(px, 0.f), (float)(IMG_W - 1));
            py = fminf(fmaxf(py, 0.f), (float)(IMG_H - 1));
            int xi = (int)px, yi = (int)py;
            unsigned n = (unsigned)(tid - b * N);
            unsigned long long key = ((unsigned long long)n << 32) |
                                     (unsigned long long)__float_as_uint(Zc);
            atomicMax(&g_keys[(size_t)b * IMG_HW + yi * IMG_W + xi], key);
        }
    }
    __shared__ float sh[256];
    sh[threadIdx.x] = err;
    __syncthreads();
    for (int s = 128; s > 0; s >>= 1) {
        if (threadIdx.x < s) sh[threadIdx.x] += sh[threadIdx.x + s];
        __syncthreads();
    }
    if (threadIdx.x == 0) atomicAdd(&g_acc[0], (double)sh[0]);
}

// ---------------------------------------------------------------------------
// K2: depth-map loss (per-(b,w) column sum over H) + scrub touched keys to 0
// ---------------------------------------------------------------------------
__global__ void __launch_bounds__(256) k2_depth(const float* __restrict__ gt_depth, int B) {
    int tid = blockIdx.x * blockDim.x + threadIdx.x;
    float derr = 0.f;
    if (tid < B * IMG_W) {
        int b = tid / IMG_W;
        int w = tid - b * IMG_W;
        size_t base = (size_t)b * IMG_HW + w;
        float s = 0.f;
        for (int h = 0; h < IMG_H; ++h) {
            size_t off = base + (size_t)h * IMG_W;
            unsigned long long k = g_keys[off];
            float d = 0.f;
            if (k) { d = __uint_as_float((unsigned)k); g_keys[off] = 0ull; }
            float diff = d - gt_depth[off];
            s = fmaf(diff, diff, s);
        }
        derr = sqrtf(s);
    }
    __shared__ float sh[256];
    sh[threadIdx.x] = derr;
    __syncthreads();
    for (int s = 128; s > 0; s >>= 1) {
        if (threadIdx.x < s) sh[threadIdx.x] += sh[threadIdx.x + s];
        __syncthreads();
    }
    if (threadIdx.x == 0) atomicAdd(&g_acc[1], (double)sh[0]);
}

// ---------------------------------------------------------------------------
// K3: combine into the 4 output scalars
// ---------------------------------------------------------------------------
__global__ void k3_final(float* __restrict__ out, int B, int N) {
    float trans = (float)g_acc[2];
    float depth = (float)((g_acc[1] / (double)IMG_W) / (double)B);
    float pcl   = (float)((g_acc[0] / (double)N) / (double)B);
    out[0] = 0.5f * trans + 1.0f * depth + 0.5f * pcl;  // (1-PC_W)*trans + DEPTH_W*depth + PC_W*pcl
    out[1] = trans;
    out[2] = depth;
    out[3] = pcl;
}

// ---------------------------------------------------------------------------
extern "C" void kernel_launch(void* const* d_in, const int* in_sizes, int n_in,
                              void* d_out, int out_size) {
    const float4* pts      = (const float4*)d_in[0];
    const float*  gt_t     = (const float*)d_in[1];
    const float*  gt_r     = (const float*)d_in[2];
    const float*  pr_t     = (const float*)d_in[3];
    const float*  pr_r     = (const float*)d_in[4];
    const float*  gt_rt    = (const float*)d_in[5];
    const float*  kmat     = (const float*)d_in[6];
    const float*  gt_depth = (const float*)d_in[7];

    int B = in_sizes[1] / 3;
    int N = in_sizes[0] / (4 * B);

    k0_prep<<<1, 32>>>(gt_t, gt_r, pr_t, pr_r, B);

    int npts = B * N;
    k1_points<<<(npts + 255) / 256, 256>>>(pts, gt_rt, kmat, B, N);

    int ncols = B * IMG_W;
    k2_depth<<<(ncols + 255) / 256, 256>>>(gt_depth, B);

    k3_final<<<1, 1>>>((float*)d_out, B, N);
}

// round 6
// speedup vs baseline: 1.5827x; 1.5827x over previous
#include <cuda_runtime.h>

#define IMG_W 1242
#define IMG_H 375
#define IMG_HW (IMG_H * IMG_W)
#define BMAX 32
#define WPAIRS 621       // IMG_W / 2
#define WTILES2 20       // ceil(621/32)

// ---- scratch (device globals: allocation-free, zero-initialized at load) ----
__device__ double g_acc[2];   // [0] sum err (pc loss), [1] sum derr (depth loss)
__device__ unsigned g_done;   // completion counter for k2 final fold
__device__ unsigned long long g_keys[(size_t)BMAX * IMG_HW];  // (n<<32)|float_bits(Z); 0 = empty

// ---------------------------------------------------------------------------
// K1: per-point transform (pred & gt), point-cloud err, project + scatter.
// Rodrigues computed per-block in shared (cheap, removes separate kernel).
// ---------------------------------------------------------------------------
__global__ void __launch_bounds__(256) k1_points(const float4* __restrict__ pts,
                                                 const float* __restrict__ pr_t,
                                                 const float* __restrict__ pr_r,
                                                 const float* __restrict__ gt_rt,   // B x 16
                                                 const float* __restrict__ kmat,    // 9
                                                 int B, int N) {
    __shared__ float sMp[12];
    __shared__ float sMg[16];
    int tid = blockIdx.x * blockDim.x + threadIdx.x;
    int b = tid / N;   // blocks never straddle batches (N % 256 == 0)

    if (threadIdx.x == 0) {
        float rx = pr_r[3*b+0], ry = pr_r[3*b+1], rz = pr_r[3*b+2];
        float th2 = rx*rx + ry*ry + rz*rz;
        float th  = sqrtf(th2);
        float A   = sinf(th) / th;
        float Bc  = (1.0f - cosf(th)) / th2;
        sMp[0]  = 1.f + Bc*(rx*rx - th2); sMp[1]  = -A*rz + Bc*rx*ry;       sMp[2]  =  A*ry + Bc*rx*rz;       sMp[3]  = pr_t[3*b+0];
        sMp[4]  =  A*rz + Bc*rx*ry;       sMp[5]  = 1.f + Bc*(ry*ry - th2); sMp[6]  = -A*rx + Bc*ry*rz;       sMp[7]  = pr_t[3*b+1];
        sMp[8]  = -A*ry + Bc*rx*rz;       sMp[9]  =  A*rx + Bc*ry*rz;       sMp[10] = 1.f + Bc*(rz*rz - th2); sMp[11] = pr_t[3*b+2];
    }
    if (threadIdx.x < 16) sMg[threadIdx.x] = gt_rt[b * 16 + threadIdx.x];
    __syncthreads();

    float err = 0.f;
    bool ok = (tid < B * N);
    float X = 0.f, Y = 0.f, Zc = 0.f;
    if (ok) {
        float4 p = pts[tid];
        X  = fmaf(sMp[0], p.x, fmaf(sMp[1], p.y, fmaf(sMp[2],  p.z, sMp[3])));
        Y  = fmaf(sMp[4], p.x, fmaf(sMp[5], p.y, fmaf(sMp[6],  p.z, sMp[7])));
        Zc = fmaf(sMp[8], p.x, fmaf(sMp[9], p.y, fmaf(sMp[10], p.z, sMp[11])));
        float Xg = fmaf(sMg[0], p.x, fmaf(sMg[1], p.y, fmaf(sMg[2],  p.z, sMg[3])));
        float Yg = fmaf(sMg[4], p.x, fmaf(sMg[5], p.y, fmaf(sMg[6],  p.z, sMg[7])));
        float Zg = fmaf(sMg[8], p.x, fmaf(sMg[9], p.y, fmaf(sMg[10], p.z, sMg[11])));
        float dx = X - Xg, dy = Y - Yg, dz = Zc - Zg;
        err = sqrtf(dx*dx + dy*dy + dz*dz);
    }

    bool act = ok && (Zc > 0.f);
    unsigned ballot = __ballot_sync(0xffffffffu, act);
    if (act) {
        float fx = kmat[0], cx = kmat[2], fy = kmat[4], cy = kmat[5];
        float px = (fx * X + cx * Zc) / Zc;
        float py = (fy * Y + cy * Zc) / Zc;
        px = fminf(fmaxf(px, 0.f), (float)(IMG_W - 1));
        py = fminf(fmaxf(py, 0.f), (float)(IMG_H - 1));
        int xi = (int)px, yi = (int)py;
        unsigned addr = (unsigned)b * (unsigned)IMG_HW + (unsigned)(yi * IMG_W + xi);
        unsigned n = (unsigned)(tid - b * N);
        // warp-aggregate: within matched pixel group, max point-index wins
        unsigned peers = __match_any_sync(ballot, addr);
        unsigned gmax  = __reduce_max_sync(peers, n);
        if (n == gmax) {
            unsigned long long key = ((unsigned long long)n << 32) |
                                     (unsigned long long)__float_as_uint(Zc);
            atomicMax(&g_keys[(size_t)addr], key);
        }
    }

    // block reduce pc err -> one double atomic per block
    #pragma unroll
    for (int o = 16; o > 0; o >>= 1) err += __shfl_down_sync(0xffffffffu, err, o);
    __shared__ float sh[8];
    if ((threadIdx.x & 31) == 0) sh[threadIdx.x >> 5] = err;
    __syncthreads();
    if (threadIdx.x == 0) {
        float t = 0.f;
        #pragma unroll
        for (int j = 0; j < 8; j++) t += sh[j];
        atomicAdd(&g_acc[0], (double)t);
    }
}

// ---------------------------------------------------------------------------
// K2: depth-map loss. Each thread owns TWO adjacent columns (vectorized
// ulonglong2 / float2 loads). Block = 32 col-pairs x 8 h-slices.
// Scrubs touched keys; streaming loads (touch-once). Last block folds the
// final combine and resets accumulators for graph replay.
// ---------------------------------------------------------------------------
__global__ void __launch_bounds__(256) k2_depth(const float* __restrict__ gt_depth,
                                                const float* __restrict__ gt_t,
                                                const float* __restrict__ gt_r,
                                                const float* __restrict__ pr_t,
                                                const float* __restrict__ pr_r,
                                                float* __restrict__ out,
                                                int B, int N) {
    int b  = blockIdx.x / WTILES2;
    int tw = blockIdx.x - b * WTILES2;
    int wp = tw * 32 + threadIdx.x;   // column-pair index

    float s0 = 0.f, s1 = 0.f;
    if (wp < WPAIRS) {
        size_t base = (size_t)b * IMG_HW + 2 * wp;   // even -> 16B aligned
        #pragma unroll 4
        for (int h = threadIdx.y; h < IMG_H; h += 8) {
            size_t off = base + (size_t)h * IMG_W;
            ulonglong2 kk = __ldcs((const ulonglong2*)&g_keys[off]);
            float2 gd = __ldcs((const float2*)&gt_depth[off]);
            float d0 = 0.f, d1 = 0.f;
            if (kk.x) d0 = __uint_as_float((unsigned)kk.x);
            if (kk.y) d1 = __uint_as_float((unsigned)kk.y);
            if (kk.x | kk.y) {
                ulonglong2 z; z.x = 0ull; z.y = 0ull;
                __stcs((ulonglong2*)&g_keys[off], z);
            }
            float f0 = d0 - gd.x, f1 = d1 - gd.y;
            s0 = fmaf(f0, f0, s0);
            s1 = fmaf(f1, f1, s1);
        }
    }

    __shared__ float sh0[8][33];
    __shared__ float sh1[8][33];
    sh0[threadIdx.y][threadIdx.x] = s0;
    sh1[threadIdx.y][threadIdx.x] = s1;
    __syncthreads();
    if (threadIdx.y == 0) {
        float t0 = 0.f, t1 = 0.f;
        #pragma unroll
        for (int j = 0; j < 8; j++) { t0 += sh0[j][threadIdx.x]; t1 += sh1[j][threadIdx.x]; }
        float derr = (wp < WPAIRS) ? (sqrtf(t0) + sqrtf(t1)) : 0.f;
        #pragma unroll
        for (int o = 16; o > 0; o >>= 1) derr += __shfl_down_sync(0xffffffffu, derr, o);
        if (threadIdx.x == 0) atomicAdd(&g_acc[1], (double)derr);
    }

    // ---- last-block final combine ----
    __shared__ int is_last;
    __threadfence();
    if (threadIdx.x == 0 && threadIdx.y == 0) {
        unsigned done = atomicAdd(&g_done, 1u);
        is_last = (done == gridDim.x - 1) ? 1 : 0;
    }
    __syncthreads();
    if (is_last && threadIdx.y == 0) {
        // transformation loss (one warp, one lane per batch)
        int lb = threadIdx.x;
        float st = 0.f, sr = 0.f;
        if (lb < B) {
            #pragma unroll
            for (int i = 0; i < 3; i++) {
                float dt = pr_t[3*lb+i] - gt_t[3*lb+i]; st += dt*dt;
                float dr = pr_r[3*lb+i] - gt_r[3*lb+i]; sr += dr*dr;
            }
        }
        #pragma unroll
        for (int o = 16; o > 0; o >>= 1) {
            st += __shfl_down_sync(0xffffffffu, st, o);
            sr += __shfl_down_sync(0xffffffffu, sr, o);
        }
        if (threadIdx.x == 0) {
            double pc_sum = atomicAdd(&g_acc[0], 0.0);
            double de_sum = atomicAdd(&g_acc[1], 0.0);
            float trans = 2.0f * (st / B) + (sr / B);   // TRANS_W=2, ROT_W=1
            float depth = (float)((de_sum / (double)IMG_W) / (double)B);
            float pcl   = (float)((pc_sum / (double)N) / (double)B);
            out[0] = 0.5f * trans + depth + 0.5f * pcl; // (1-PC_W)*trans + DEPTH_W*depth + PC_W*pcl
            out[1] = trans;
            out[2] = depth;
            out[3] = pcl;
            // reset for next graph replay
            g_acc[0] = 0.0;
            g_acc[1] = 0.0;
            g_done = 0u;
        }
    }
}

// ---------------------------------------------------------------------------
extern "C" void kernel_launch(void* const* d_in, const int* in_sizes, int n_in,
                              void* d_out, int out_size) {
    const float4* pts      = (const float4*)d_in[0];
    const float*  gt_t     = (const float*)d_in[1];
    const float*  gt_r     = (const float*)d_in[2];
    const float*  pr_t     = (const float*)d_in[3];
    const float*  pr_r     = (const float*)d_in[4];
    const float*  gt_rt    = (const float*)d_in[5];
    const float*  kmat     = (const float*)d_in[6];
    const float*  gt_depth = (const float*)d_in[7];

    int B = in_sizes[1] / 3;
    int N = in_sizes[0] / (4 * B);

    int npts = B * N;
    k1_points<<<(npts + 255) / 256, 256>>>(pts, pr_t, pr_r, gt_rt, kmat, B, N);

    dim3 blk(32, 8);
    k2_depth<<<B * WTILES2, blk>>>(gt_depth, gt_t, gt_r, pr_t, pr_r, (float*)d_out, B, N);
}